// round 11
// baseline (speedup 1.0000x reference)
#include <cuda_runtime.h>
#include <cstdint>

// Problem constants (fixed by dataset).
#define U_C  100000
#define I_C  50000
#define N_C  150000
#define ROWS_TOT (N_C + U_C + I_C)       // 300000
#define CAP  24                          // perm = 57.6MB -> L2-resident
#define OVF_CAP 65536

#define TPB 256
#define D64 64

__device__ int  d_curs[ROWS_TOT];
__device__ int2 d_perm[(size_t)ROWS_TOT * CAP];
__device__ int  d_ovf_count;
__device__ int4 d_ovf[OVF_CAP];          // {key, col, val_bits, 0}

// ---------------- build: direct-indexed scatter ----------------
__global__ void __launch_bounds__(TPB) scatter_list(const int* __restrict__ rows,
                                                    const int* __restrict__ cols,
                                                    const float* __restrict__ vals,
                                                    int E, int key_base) {
    int e = blockIdx.x * TPB + threadIdx.x;
    if (e >= E) return;
    int key = key_base + __ldcs(rows + e);
    int c   = __ldcs(cols + e);
    float v = __ldcs(vals + e);
    int pos = atomicAdd(&d_curs[key], 1);
    if (pos < CAP) {
        d_perm[(size_t)key * CAP + pos] = make_int2(c, __float_as_int(v));
    } else {
        int o = atomicAdd(&d_ovf_count, 1);
        if (o < OVF_CAP) d_ovf[o] = make_int4(key, c, __float_as_int(v), 0);
    }
}

// user + item lists fused into one launch (direct index).
__global__ void __launch_bounds__(TPB) scatter_ui(const int* __restrict__ ur,
                                                  const int* __restrict__ uc,
                                                  const float* __restrict__ uv,
                                                  const int* __restrict__ ir,
                                                  const int* __restrict__ ic,
                                                  const float* __restrict__ iv,
                                                  int EU, int EI, int N_, int U_) {
    int e = blockIdx.x * TPB + threadIdx.x;
    if (e >= EU + EI) return;
    int key, c; float v;
    if (e < EU) {
        key = N_ + __ldcs(ur + e);       c = __ldcs(uc + e);  v = __ldcs(uv + e);
    } else {
        int k = e - EU;
        key = N_ + U_ + __ldcs(ir + k);  c = __ldcs(ic + k);  v = __ldcs(iv + k);
    }
    int pos = atomicAdd(&d_curs[key], 1);
    if (pos < CAP) {
        d_perm[(size_t)key * CAP + pos] = make_int2(c, __float_as_int(v));
    } else {
        int o = atomicAdd(&d_ovf_count, 1);
        if (o < OVF_CAP) d_ovf[o] = make_int4(key, c, __float_as_int(v), 0);
    }
}

// ---------------- main: register-resident bucket + shfl broadcast -----------
// 16 threads per row. Bucket (<=24 int2) loaded with ONE coalesced pass into
// registers (b0 across 16 lanes, b1 across lanes 0-7), then broadcast per-edge
// via shfl. All gathers within a chunk of 8 are independent -> MLP=8.

// One chunk of up to 8 edges. SRC = register holding bucket entries,
// SRCOFF = lane offset of entry 0 within the 16-lane group, BASEJ = global j.
#define CHUNK8(SRC, BASEJ, SRCOFF)                                             \
    _Pragma("unroll")                                                          \
    for (int j = 0; j < 8; j++) {                                              \
        int c_  = __shfl_sync(0xffffffffu, (SRC).x, base_lane + (SRCOFF) + j); \
        int vb_ = __shfl_sync(0xffffffffu, (SRC).y, base_lane + (SRCOFF) + j); \
        if ((BASEJ) + j < deg) {                                               \
            const float* p_ = (c_ < U_split)                                   \
                ? src0 + (long long)c_ * D64                                   \
                : src1 + (long long)(c_ - U_split) * D64;                      \
            float4 x_ = reinterpret_cast<const float4*>(p_)[lane16];           \
            float v_ = __int_as_float(vb_);                                    \
            acc.x = fmaf(v_, x_.x, acc.x); acc.y = fmaf(v_, x_.y, acc.y);      \
            acc.z = fmaf(v_, x_.z, acc.z); acc.w = fmaf(v_, x_.w, acc.w);      \
        }                                                                      \
    }

__global__ void __launch_bounds__(TPB) csr_spmm_range(const float* __restrict__ user_emb,
                                                      const float* __restrict__ item_emb,
                                                      float* __restrict__ out,
                                                      int row_base, int n_rows,
                                                      int N_, int U_) {
    int tid    = blockIdx.x * TPB + threadIdx.x;
    int rr     = tid >> 4;
    int lane16 = tid & 15;
    if (rr >= n_rows) return;   // never taken: n_rows*16 is a multiple of TPB
    int key = row_base + rr;

    int warp_lane = threadIdx.x & 31;
    int base_lane = warp_lane & 16;      // 0 for lanes 0-15, 16 for lanes 16-31

    const float* src0;
    const float* src1;
    int U_split;
    if (key < N_) {                    // graph: concat(user, item) source
        src0 = user_emb; src1 = item_emb; U_split = U_;
    } else if (key < N_ + U_) {        // user SpMM
        src0 = user_emb; src1 = user_emb; U_split = 0x7FFFFFFF;
    } else {                           // item SpMM
        src0 = item_emb; src1 = item_emb; U_split = 0x7FFFFFFF;
    }

    int deg = min(d_curs[key], CAP);
    const int2* bucket = d_perm + (size_t)key * CAP;

    // Cooperative coalesced bucket load into registers.
    int2 b0 = __ldcs(bucket + lane16);                                   // entries 0..15
    int2 b1 = (lane16 < CAP - 16) ? __ldcs(bucket + 16 + lane16)
                                  : make_int2(0, 0);                      // entries 16..23

    // Warp-uniform chunk predicate (two rows per warp may differ in deg;
    // shfl_sync needs full-warp participation).
    int deg_other = __shfl_xor_sync(0xffffffffu, deg, 16);
    int degw = max(deg, deg_other);

    float4 acc = make_float4(0.f, 0.f, 0.f, 0.f);

    CHUNK8(b0, 0, 0);
    if (degw > 8)  { CHUNK8(b0, 8, 8); }
    if (degw > 16) { CHUNK8(b1, 16, 0); }

    __stcs(reinterpret_cast<float4*>(out + (long long)key * D64) + lane16, acc);
}

// ---------------- overflow fixup (exactness; small) ----------------
__global__ void __launch_bounds__(TPB) fixup(const float* __restrict__ user_emb,
                                             const float* __restrict__ item_emb,
                                             float* __restrict__ out,
                                             int N_, int U_) {
    int n = min(d_ovf_count, OVF_CAP);
    long long total = (long long)n * 16;
    for (long long t = blockIdx.x * (long long)TPB + threadIdx.x; t < total;
         t += (long long)gridDim.x * TPB) {
        int idx  = (int)(t >> 4);
        int lane = (int)(t & 15);
        int4 e = d_ovf[idx];
        int key = e.x, c = e.y;
        float v = __int_as_float(e.z);
        const float* src;
        if (key < N_)            src = (c < U_) ? user_emb + (long long)c * D64
                                                : item_emb + (long long)(c - U_) * D64;
        else if (key < N_ + U_)  src = user_emb + (long long)c * D64;
        else                     src = item_emb + (long long)c * D64;
        float4 x = reinterpret_cast<const float4*>(src)[lane];
        x.x *= v; x.y *= v; x.z *= v; x.w *= v;
        float4* d = reinterpret_cast<float4*>(out + (long long)key * D64) + lane;
        asm volatile("red.global.add.v4.f32 [%0], {%1,%2,%3,%4};"
                     :: "l"(d), "f"(x.x), "f"(x.y), "f"(x.z), "f"(x.w)
                     : "memory");
    }
}

extern "C" void kernel_launch(void* const* d_in, const int* in_sizes, int n_in,
                              void* d_out, int out_size) {
    const float* user_emb = (const float*)d_in[0];
    const float* item_emb = (const float*)d_in[1];
    const int*   g_rows = (const int*)d_in[2];
    const int*   g_cols = (const int*)d_in[3];
    const float* g_vals = (const float*)d_in[4];
    const int*   u_rows = (const int*)d_in[5];
    const int*   u_cols = (const int*)d_in[6];
    const float* u_vals = (const float*)d_in[7];
    const int*   i_rows = (const int*)d_in[8];
    const int*   i_cols = (const int*)d_in[9];
    const float* i_vals = (const float*)d_in[10];

    float* out = (float*)d_out;

    const int U_ = in_sizes[0] / D64;   // 100000
    const int I_ = in_sizes[1] / D64;   // 50000
    const int N_ = U_ + I_;
    const int EG = in_sizes[2];
    const int EU = in_sizes[5];
    const int EI = in_sizes[8];
    const int ROWS = N_ + U_ + I_;

    // Zero cursors + overflow counter.
    void* curs_ptr = nullptr;
    cudaGetSymbolAddress(&curs_ptr, d_curs);
    cudaMemsetAsync(curs_ptr, 0, (size_t)ROWS * sizeof(int), 0);
    void* ovf_ptr = nullptr;
    cudaGetSymbolAddress(&ovf_ptr, d_ovf_count);
    cudaMemsetAsync(ovf_ptr, 0, sizeof(int), 0);

    // Build (serial; both scatters bind on the same wavefront resource).
    {
        int ET = EU + EI;
        scatter_ui<<<(ET + TPB - 1) / TPB, TPB>>>(u_rows, u_cols, u_vals,
                                                  i_rows, i_cols, i_vals,
                                                  EU, EI, N_, U_);
    }
    scatter_list<<<(EG + TPB - 1) / TPB, TPB>>>(g_rows, g_cols, g_vals, EG, 0);

    // Mains.
    {
        int n_rows = U_ + I_;
        int blocks = (n_rows * 16 + TPB - 1) / TPB;
        csr_spmm_range<<<blocks, TPB>>>(user_emb, item_emb, out, N_, n_rows, N_, U_);
    }
    {
        int blocks = (N_ * 16 + TPB - 1) / TPB;
        csr_spmm_range<<<blocks, TPB>>>(user_emb, item_emb, out, 0, N_, N_, U_);
    }

    // Exact overflow fixup.
    fixup<<<64, TPB>>>(user_emb, item_emb, out, N_, U_);
}

// round 12
// speedup vs baseline: 1.0207x; 1.0207x over previous
#include <cuda_runtime.h>
#include <cstdint>

// Problem constants (fixed by dataset).
#define U_C  100000
#define I_C  50000
#define N_C  150000
#define ROWS_TOT (N_C + U_C + I_C)       // 300000
#define CAP  24                          // perm = 57.6MB -> L2-resident
#define OVF_CAP 65536

#define TPB 256
#define D64 64
#define SCAT_BLOCKS 2368                 // scatter sub-grid in the fused P2 kernel

__device__ int  d_curs[ROWS_TOT];
__device__ int2 d_perm[(size_t)ROWS_TOT * CAP];
__device__ int  d_ovf_count;
__device__ int4 d_ovf[OVF_CAP];          // {key, col, val_bits, 0}

// ---------------- scatter helper ----------------
__device__ __forceinline__ void scatter_edge(int key, int c, float v) {
    int pos = atomicAdd(&d_curs[key], 1);
    if (pos < CAP) {
        d_perm[(size_t)key * CAP + pos] = make_int2(c, __float_as_int(v));
    } else {
        int o = atomicAdd(&d_ovf_count, 1);
        if (o < OVF_CAP) d_ovf[o] = make_int4(key, c, __float_as_int(v), 0);
    }
}

// ---------------- P1: graph scatter (direct index, full machine) ------------
__global__ void __launch_bounds__(TPB) scatter_g(const int* __restrict__ rows,
                                                 const int* __restrict__ cols,
                                                 const float* __restrict__ vals,
                                                 int E) {
    int e = blockIdx.x * TPB + threadIdx.x;
    if (e >= E) return;
    scatter_edge(__ldcs(rows + e), __ldcs(cols + e), __ldcs(vals + e));
}

// ---------------- main row processing (shuffle-broadcast bucket) ------------
__device__ __forceinline__ void process_row(int key, int lane16, int base_lane,
                                            const float* __restrict__ src0,
                                            const float* __restrict__ src1,
                                            int U_split,
                                            float* __restrict__ out) {
    int deg = min(d_curs[key], CAP);
    const int2* bucket = d_perm + (size_t)key * CAP;

    // Cooperative coalesced bucket load into registers.
    int2 b0 = __ldcs(bucket + lane16);                                // entries 0..15
    int2 b1 = (lane16 < CAP - 16) ? __ldcs(bucket + 16 + lane16)
                                  : make_int2(0, 0);                  // entries 16..23

    // Warp-uniform chunk predicate (two rows per warp).
    int deg_other = __shfl_xor_sync(0xffffffffu, deg, 16);
    int degw = max(deg, deg_other);

    float4 acc = make_float4(0.f, 0.f, 0.f, 0.f);

#define CHUNK8(SRC, BASEJ, SRCOFF)                                             \
    _Pragma("unroll")                                                          \
    for (int j = 0; j < 8; j++) {                                              \
        int c_  = __shfl_sync(0xffffffffu, (SRC).x, base_lane + (SRCOFF) + j); \
        int vb_ = __shfl_sync(0xffffffffu, (SRC).y, base_lane + (SRCOFF) + j); \
        if ((BASEJ) + j < deg) {                                               \
            const float* p_ = (c_ < U_split)                                   \
                ? src0 + (long long)c_ * D64                                   \
                : src1 + (long long)(c_ - U_split) * D64;                      \
            float4 x_ = reinterpret_cast<const float4*>(p_)[lane16];           \
            float v_ = __int_as_float(vb_);                                    \
            acc.x = fmaf(v_, x_.x, acc.x); acc.y = fmaf(v_, x_.y, acc.y);      \
            acc.z = fmaf(v_, x_.z, acc.z); acc.w = fmaf(v_, x_.w, acc.w);      \
        }                                                                      \
    }

    CHUNK8(b0, 0, 0);
    if (degw > 8)  { CHUNK8(b0, 8, 8); }
    if (degw > 16) { CHUNK8(b1, 16, 0); }
#undef CHUNK8

    __stcs(reinterpret_cast<float4*>(out + (long long)key * D64) + lane16, acc);
}

// ---------------- P2: fused scatterUI + mainG --------------------------------
// Blocks [0, SCAT_BLOCKS): grid-stride scatter of user+item edge lists.
// Blocks [SCAT_BLOCKS, ...): graph main over rows [0, N_).
// Disjoint state: scatter writes UI buckets/cursors (keys >= N_), main reads
// graph buckets/cursors (keys < N_).
__global__ void __launch_bounds__(TPB) fused_scatui_maing(
        const int* __restrict__ ur, const int* __restrict__ uc, const float* __restrict__ uv,
        const int* __restrict__ ir, const int* __restrict__ ic, const float* __restrict__ iv,
        int EU, int EI,
        const float* __restrict__ user_emb,
        const float* __restrict__ item_emb,
        float* __restrict__ out,
        int N_, int U_) {
    if (blockIdx.x < SCAT_BLOCKS) {
        int ET = EU + EI;
        for (int e = blockIdx.x * TPB + threadIdx.x; e < ET; e += SCAT_BLOCKS * TPB) {
            int key, c; float v;
            if (e < EU) {
                key = N_ + __ldcs(ur + e);       c = __ldcs(uc + e);  v = __ldcs(uv + e);
            } else {
                int k = e - EU;
                key = N_ + U_ + __ldcs(ir + k);  c = __ldcs(ic + k);  v = __ldcs(iv + k);
            }
            scatter_edge(key, c, v);
        }
    } else {
        int tid    = (blockIdx.x - SCAT_BLOCKS) * TPB + threadIdx.x;
        int rr     = tid >> 4;
        int lane16 = tid & 15;
        if (rr >= N_) return;
        int base_lane = threadIdx.x & 16;
        process_row(rr, lane16, base_lane, user_emb, item_emb, U_, out);
    }
}

// ---------------- P3: user+item main ----------------------------------------
__global__ void __launch_bounds__(TPB) main_ui(const float* __restrict__ user_emb,
                                               const float* __restrict__ item_emb,
                                               float* __restrict__ out,
                                               int N_, int U_, int I_) {
    int tid    = blockIdx.x * TPB + threadIdx.x;
    int rr     = tid >> 4;
    int lane16 = tid & 15;
    if (rr >= U_ + I_) return;
    int key = N_ + rr;
    int base_lane = threadIdx.x & 16;

    const float* src = (key < N_ + U_) ? user_emb : item_emb;
    process_row(key, lane16, base_lane, src, src, 0x7FFFFFFF, out);
}

// ---------------- overflow fixup (exactness; small) ----------------
__global__ void __launch_bounds__(TPB) fixup(const float* __restrict__ user_emb,
                                             const float* __restrict__ item_emb,
                                             float* __restrict__ out,
                                             int N_, int U_) {
    int n = min(d_ovf_count, OVF_CAP);
    long long total = (long long)n * 16;
    for (long long t = blockIdx.x * (long long)TPB + threadIdx.x; t < total;
         t += (long long)gridDim.x * TPB) {
        int idx  = (int)(t >> 4);
        int lane = (int)(t & 15);
        int4 e = d_ovf[idx];
        int key = e.x, c = e.y;
        float v = __int_as_float(e.z);
        const float* src;
        if (key < N_)            src = (c < U_) ? user_emb + (long long)c * D64
                                                : item_emb + (long long)(c - U_) * D64;
        else if (key < N_ + U_)  src = user_emb + (long long)c * D64;
        else                     src = item_emb + (long long)c * D64;
        float4 x = reinterpret_cast<const float4*>(src)[lane];
        x.x *= v; x.y *= v; x.z *= v; x.w *= v;
        float4* d = reinterpret_cast<float4*>(out + (long long)key * D64) + lane;
        asm volatile("red.global.add.v4.f32 [%0], {%1,%2,%3,%4};"
                     :: "l"(d), "f"(x.x), "f"(x.y), "f"(x.z), "f"(x.w)
                     : "memory");
    }
}

extern "C" void kernel_launch(void* const* d_in, const int* in_sizes, int n_in,
                              void* d_out, int out_size) {
    const float* user_emb = (const float*)d_in[0];
    const float* item_emb = (const float*)d_in[1];
    const int*   g_rows = (const int*)d_in[2];
    const int*   g_cols = (const int*)d_in[3];
    const float* g_vals = (const float*)d_in[4];
    const int*   u_rows = (const int*)d_in[5];
    const int*   u_cols = (const int*)d_in[6];
    const float* u_vals = (const float*)d_in[7];
    const int*   i_rows = (const int*)d_in[8];
    const int*   i_cols = (const int*)d_in[9];
    const float* i_vals = (const float*)d_in[10];

    float* out = (float*)d_out;

    const int U_ = in_sizes[0] / D64;   // 100000
    const int I_ = in_sizes[1] / D64;   // 50000
    const int N_ = U_ + I_;
    const int EG = in_sizes[2];
    const int EU = in_sizes[5];
    const int EI = in_sizes[8];
    const int ROWS = N_ + U_ + I_;

    // Zero cursors + overflow counter.
    void* curs_ptr = nullptr;
    cudaGetSymbolAddress(&curs_ptr, d_curs);
    cudaMemsetAsync(curs_ptr, 0, (size_t)ROWS * sizeof(int), 0);
    void* ovf_ptr = nullptr;
    cudaGetSymbolAddress(&ovf_ptr, d_ovf_count);
    cudaMemsetAsync(ovf_ptr, 0, sizeof(int), 0);

    // P1: graph scatter, full machine.
    scatter_g<<<(EG + TPB - 1) / TPB, TPB>>>(g_rows, g_cols, g_vals, EG);

    // P2: fused scatterUI (first SCAT_BLOCKS blocks) + graph main (rest).
    {
        int main_blocks = (N_ * 16 + TPB - 1) / TPB;   // 9375
        fused_scatui_maing<<<SCAT_BLOCKS + main_blocks, TPB>>>(
            u_rows, u_cols, u_vals, i_rows, i_cols, i_vals,
            EU, EI, user_emb, item_emb, out, N_, U_);
    }

    // P3: user+item main.
    {
        int n_rows = U_ + I_;
        int blocks = (n_rows * 16 + TPB - 1) / TPB;
        main_ui<<<blocks, TPB>>>(user_emb, item_emb, out, N_, U_, I_);
    }

    // Exact overflow fixup.
    fixup<<<64, TPB>>>(user_emb, item_emb, out, N_, U_);
}

// round 13
// speedup vs baseline: 1.1395x; 1.1164x over previous
#include <cuda_runtime.h>
#include <cstdint>

// Problem constants (fixed by dataset).
#define U_C  100000
#define I_C  50000
#define N_C  150000
#define ROWS_TOT (N_C + U_C + I_C)       // 300000
#define CAP  24                          // perm = 57.6MB -> L2-resident
#define OVF_CAP 65536

#define TPB 256
#define D64 64

// P2 interleave: grid = 4*3125 = 12500 blocks.
//   blockIdx % 4 == 3  -> scatterUI role (3125 blocks, grid-stride over EU+EI)
//   otherwise          -> mainG role (9375 blocks; 16 rows each = 150000 rows)
#define P2_GROUPS 3125
#define P2_BLOCKS (P2_GROUPS * 4)

__device__ int  d_curs[ROWS_TOT];
__device__ int2 d_perm[(size_t)ROWS_TOT * CAP];
__device__ int  d_ovf_count;
__device__ int4 d_ovf[OVF_CAP];          // {key, col, val_bits, 0}

// ---------------- scatter helper ----------------
__device__ __forceinline__ void scatter_edge(int key, int c, float v) {
    int pos = atomicAdd(&d_curs[key], 1);
    if (pos < CAP) {
        d_perm[(size_t)key * CAP + pos] = make_int2(c, __float_as_int(v));
    } else {
        int o = atomicAdd(&d_ovf_count, 1);
        if (o < OVF_CAP) d_ovf[o] = make_int4(key, c, __float_as_int(v), 0);
    }
}

// ---------------- P1: graph scatter (direct index, full machine) ------------
__global__ void __launch_bounds__(TPB) scatter_g(const int* __restrict__ rows,
                                                 const int* __restrict__ cols,
                                                 const float* __restrict__ vals,
                                                 int E) {
    int e = blockIdx.x * TPB + threadIdx.x;
    if (e >= E) return;
    scatter_edge(__ldcs(rows + e), __ldcs(cols + e), __ldcs(vals + e));
}

// ---------------- main row processing (shuffle-broadcast bucket) ------------
__device__ __forceinline__ void process_row(int key, int lane16, int base_lane,
                                            const float* __restrict__ src0,
                                            const float* __restrict__ src1,
                                            int U_split,
                                            float* __restrict__ out) {
    int deg = min(d_curs[key], CAP);
    const int2* bucket = d_perm + (size_t)key * CAP;

    // Cooperative coalesced bucket load into registers.
    int2 b0 = __ldcs(bucket + lane16);                                // entries 0..15
    int2 b1 = (lane16 < CAP - 16) ? __ldcs(bucket + 16 + lane16)
                                  : make_int2(0, 0);                  // entries 16..23

    // Warp-uniform chunk predicate (two rows per warp).
    int deg_other = __shfl_xor_sync(0xffffffffu, deg, 16);
    int degw = max(deg, deg_other);

    float4 acc = make_float4(0.f, 0.f, 0.f, 0.f);

#define CHUNK8(SRC, BASEJ, SRCOFF)                                             \
    _Pragma("unroll")                                                          \
    for (int j = 0; j < 8; j++) {                                              \
        int c_  = __shfl_sync(0xffffffffu, (SRC).x, base_lane + (SRCOFF) + j); \
        int vb_ = __shfl_sync(0xffffffffu, (SRC).y, base_lane + (SRCOFF) + j); \
        if ((BASEJ) + j < deg) {                                               \
            const float* p_ = (c_ < U_split)                                   \
                ? src0 + (long long)c_ * D64                                   \
                : src1 + (long long)(c_ - U_split) * D64;                      \
            float4 x_ = reinterpret_cast<const float4*>(p_)[lane16];           \
            float v_ = __int_as_float(vb_);                                    \
            acc.x = fmaf(v_, x_.x, acc.x); acc.y = fmaf(v_, x_.y, acc.y);      \
            acc.z = fmaf(v_, x_.z, acc.z); acc.w = fmaf(v_, x_.w, acc.w);      \
        }                                                                      \
    }

    CHUNK8(b0, 0, 0);
    if (degw > 8)  { CHUNK8(b0, 8, 8); }
    if (degw > 16) { CHUNK8(b1, 16, 0); }
#undef CHUNK8

    __stcs(reinterpret_cast<float4*>(out + (long long)key * D64) + lane16, acc);
}

// ---------------- P2: interleaved scatterUI + mainG --------------------------
// Role assigned by blockIdx % 4 so every resident wave carries both kinds.
__global__ void __launch_bounds__(TPB) fused_scatui_maing(
        const int* __restrict__ ur, const int* __restrict__ uc, const float* __restrict__ uv,
        const int* __restrict__ ir, const int* __restrict__ ic, const float* __restrict__ iv,
        int EU, int EI,
        const float* __restrict__ user_emb,
        const float* __restrict__ item_emb,
        float* __restrict__ out,
        int N_, int U_) {
    int group = blockIdx.x >> 2;
    int role  = blockIdx.x & 3;

    if (role == 3) {
        // Scatter role: grid-stride over user+item edges.
        int ET = EU + EI;
        for (int e = group * TPB + threadIdx.x; e < ET; e += P2_GROUPS * TPB) {
            int key, c; float v;
            if (e < EU) {
                key = N_ + __ldcs(ur + e);       c = __ldcs(uc + e);  v = __ldcs(uv + e);
            } else {
                int k = e - EU;
                key = N_ + U_ + __ldcs(ir + k);  c = __ldcs(ic + k);  v = __ldcs(iv + k);
            }
            scatter_edge(key, c, v);
        }
    } else {
        // Main role over graph rows [0, N_).
        int mblk   = group * 3 + role;           // 0 .. 9374
        int tid    = mblk * TPB + threadIdx.x;
        int rr     = tid >> 4;
        int lane16 = tid & 15;
        if (rr >= N_) return;
        int base_lane = threadIdx.x & 16;
        process_row(rr, lane16, base_lane, user_emb, item_emb, U_, out);
    }
}

// ---------------- P3: user+item main ----------------------------------------
__global__ void __launch_bounds__(TPB) main_ui(const float* __restrict__ user_emb,
                                               const float* __restrict__ item_emb,
                                               float* __restrict__ out,
                                               int N_, int U_, int I_) {
    int tid    = blockIdx.x * TPB + threadIdx.x;
    int rr     = tid >> 4;
    int lane16 = tid & 15;
    if (rr >= U_ + I_) return;
    int key = N_ + rr;
    int base_lane = threadIdx.x & 16;

    const float* src = (key < N_ + U_) ? user_emb : item_emb;
    process_row(key, lane16, base_lane, src, src, 0x7FFFFFFF, out);
}

// ---------------- overflow fixup (exactness; ~12K edges expected) -----------
__global__ void __launch_bounds__(TPB) fixup(const float* __restrict__ user_emb,
                                             const float* __restrict__ item_emb,
                                             float* __restrict__ out,
                                             int N_, int U_) {
    int n = min(d_ovf_count, OVF_CAP);
    long long total = (long long)n * 16;
    for (long long t = blockIdx.x * (long long)TPB + threadIdx.x; t < total;
         t += (long long)gridDim.x * TPB) {
        int idx  = (int)(t >> 4);
        int lane = (int)(t & 15);
        int4 e = d_ovf[idx];
        int key = e.x, c = e.y;
        float v = __int_as_float(e.z);
        const float* src;
        if (key < N_)            src = (c < U_) ? user_emb + (long long)c * D64
                                                : item_emb + (long long)(c - U_) * D64;
        else if (key < N_ + U_)  src = user_emb + (long long)c * D64;
        else                     src = item_emb + (long long)c * D64;
        float4 x = reinterpret_cast<const float4*>(src)[lane];
        x.x *= v; x.y *= v; x.z *= v; x.w *= v;
        float4* d = reinterpret_cast<float4*>(out + (long long)key * D64) + lane;
        asm volatile("red.global.add.v4.f32 [%0], {%1,%2,%3,%4};"
                     :: "l"(d), "f"(x.x), "f"(x.y), "f"(x.z), "f"(x.w)
                     : "memory");
    }
}

extern "C" void kernel_launch(void* const* d_in, const int* in_sizes, int n_in,
                              void* d_out, int out_size) {
    const float* user_emb = (const float*)d_in[0];
    const float* item_emb = (const float*)d_in[1];
    const int*   g_rows = (const int*)d_in[2];
    const int*   g_cols = (const int*)d_in[3];
    const float* g_vals = (const float*)d_in[4];
    const int*   u_rows = (const int*)d_in[5];
    const int*   u_cols = (const int*)d_in[6];
    const float* u_vals = (const float*)d_in[7];
    const int*   i_rows = (const int*)d_in[8];
    const int*   i_cols = (const int*)d_in[9];
    const float* i_vals = (const float*)d_in[10];

    float* out = (float*)d_out;

    const int U_ = in_sizes[0] / D64;   // 100000
    const int I_ = in_sizes[1] / D64;   // 50000
    const int N_ = U_ + I_;
    const int EG = in_sizes[2];
    const int EU = in_sizes[5];
    const int EI = in_sizes[8];
    const int ROWS = N_ + U_ + I_;

    // Zero cursors + overflow counter.
    void* curs_ptr = nullptr;
    cudaGetSymbolAddress(&curs_ptr, d_curs);
    cudaMemsetAsync(curs_ptr, 0, (size_t)ROWS * sizeof(int), 0);
    void* ovf_ptr = nullptr;
    cudaGetSymbolAddress(&ovf_ptr, d_ovf_count);
    cudaMemsetAsync(ovf_ptr, 0, sizeof(int), 0);

    // P1: graph scatter, full machine.
    scatter_g<<<(EG + TPB - 1) / TPB, TPB>>>(g_rows, g_cols, g_vals, EG);

    // P2: interleaved scatterUI + graph main.
    fused_scatui_maing<<<P2_BLOCKS, TPB>>>(
        u_rows, u_cols, u_vals, i_rows, i_cols, i_vals,
        EU, EI, user_emb, item_emb, out, N_, U_);

    // P3: user+item main.
    {
        int n_rows = U_ + I_;
        int blocks = (n_rows * 16 + TPB - 1) / TPB;
        main_ui<<<blocks, TPB>>>(user_emb, item_emb, out, N_, U_, I_);
    }

    // Exact overflow fixup (wide grid; ~1 item per thread).
    fixup<<<1024, TPB>>>(user_emb, item_emb, out, N_, U_);
}

// round 14
// speedup vs baseline: 1.3063x; 1.1464x over previous
#include <cuda_runtime.h>
#include <cuda_fp16.h>
#include <cstdint>

// Problem constants (fixed by dataset).
#define U_C  100000
#define I_C  50000
#define N_C  150000
#define ROWS_TOT (N_C + U_C + I_C)       // 300000
#define CAP  24
#define OVF_CAP 65536

#define TPB 256
#define D64 64

// Interleaved kernels: grid = 4*3125; role = blockIdx & 3.
#define GROUPS 3125
#define IBLOCKS (GROUPS * 4)

__device__ int  d_curs[ROWS_TOT];
__device__ int2 d_perm[(size_t)ROWS_TOT * CAP];
__device__ int  d_ovf_count;
__device__ int4 d_ovf[OVF_CAP];                      // {key, col(unified), val_bits, 0}
__device__ __align__(16) uint2 d_emb16[(size_t)N_C * 16];  // fp16 unified table: row = 16 uint2 = 128B

// ---------------- scatter helper ----------------
__device__ __forceinline__ void scatter_edge(int key, int c, float v) {
    int pos = atomicAdd(&d_curs[key], 1);
    if (pos < CAP) {
        d_perm[(size_t)key * CAP + pos] = make_int2(c, __float_as_int(v));
    } else {
        int o = atomicAdd(&d_ovf_count, 1);
        if (o < OVF_CAP) d_ovf[o] = make_int4(key, c, __float_as_int(v), 0);
    }
}

// ---------------- P1: convert (role 3) interleaved with scatterG ------------
// Convert: fp32 concat(user,item) -> fp16 unified table. 9.6M floats in
// chunks of 8 (one uint4 store). Chunks never straddle the user/item split
// (6.4M % 8 == 0).
__global__ void __launch_bounds__(TPB) p1_convert_scatg(
        const float* __restrict__ user_emb, const float* __restrict__ item_emb,
        const int* __restrict__ gr, const int* __restrict__ gc, const float* __restrict__ gv,
        int EG, int U_) {
    int group = blockIdx.x >> 2;
    int role  = blockIdx.x & 3;

    if (role == 3) {
        const int UCHUNKS = U_ * 8;            // user chunks (8 floats each)
        const int NCHUNKS = N_C * 8;           // total chunks
        for (int idx = group * TPB + threadIdx.x; idx < NCHUNKS; idx += GROUPS * TPB) {
            const float4* src = (idx < UCHUNKS)
                ? reinterpret_cast<const float4*>(user_emb) + (size_t)idx * 2
                : reinterpret_cast<const float4*>(item_emb) + (size_t)(idx - UCHUNKS) * 2;
            float4 a = __ldcs(src);
            float4 b = __ldcs(src + 1);
            __half2 h0 = __floats2half2_rn(a.x, a.y);
            __half2 h1 = __floats2half2_rn(a.z, a.w);
            __half2 h2 = __floats2half2_rn(b.x, b.y);
            __half2 h3 = __floats2half2_rn(b.z, b.w);
            uint4 w;
            w.x = *reinterpret_cast<unsigned int*>(&h0);
            w.y = *reinterpret_cast<unsigned int*>(&h1);
            w.z = *reinterpret_cast<unsigned int*>(&h2);
            w.w = *reinterpret_cast<unsigned int*>(&h3);
            reinterpret_cast<uint4*>(d_emb16)[idx] = w;
        }
    } else {
        int e = (group * 3 + role) * TPB + threadIdx.x;
        if (e >= EG) return;
        scatter_edge(__ldcs(gr + e), __ldcs(gc + e), __ldcs(gv + e));
    }
}

// ---------------- main row processing (fp16 gather, shfl-broadcast bucket) --
__device__ __forceinline__ void process_row(int key, int lane16, int base_lane,
                                            float* __restrict__ out) {
    int deg = min(d_curs[key], CAP);
    const int2* bucket = d_perm + (size_t)key * CAP;

    int2 b0 = __ldcs(bucket + lane16);
    int2 b1 = (lane16 < CAP - 16) ? __ldcs(bucket + 16 + lane16) : make_int2(0, 0);

    int deg_other = __shfl_xor_sync(0xffffffffu, deg, 16);
    int degw = max(deg, deg_other);

    float4 acc = make_float4(0.f, 0.f, 0.f, 0.f);

#define CHUNK8(SRC, BASEJ, SRCOFF)                                             \
    _Pragma("unroll")                                                          \
    for (int j = 0; j < 8; j++) {                                              \
        int c_  = __shfl_sync(0xffffffffu, (SRC).x, base_lane + (SRCOFF) + j); \
        int vb_ = __shfl_sync(0xffffffffu, (SRC).y, base_lane + (SRCOFF) + j); \
        if ((BASEJ) + j < deg) {                                               \
            uint2 g_ = d_emb16[(size_t)c_ * 16 + lane16];                      \
            float2 f0_ = __half22float2(*reinterpret_cast<__half2*>(&g_.x));   \
            float2 f1_ = __half22float2(*reinterpret_cast<__half2*>(&g_.y));   \
            float v_ = __int_as_float(vb_);                                    \
            acc.x = fmaf(v_, f0_.x, acc.x); acc.y = fmaf(v_, f0_.y, acc.y);    \
            acc.z = fmaf(v_, f1_.x, acc.z); acc.w = fmaf(v_, f1_.y, acc.w);    \
        }                                                                      \
    }

    CHUNK8(b0, 0, 0);
    if (degw > 8)  { CHUNK8(b0, 8, 8); }
    if (degw > 16) { CHUNK8(b1, 16, 0); }
#undef CHUNK8

    __stcs(reinterpret_cast<float4*>(out + (long long)key * D64) + lane16, acc);
}

// ---------------- P2: interleaved scatterUI (role 3) + mainG ----------------
__global__ void __launch_bounds__(TPB) p2_scatui_maing(
        const int* __restrict__ ur, const int* __restrict__ uc, const float* __restrict__ uv,
        const int* __restrict__ ir, const int* __restrict__ ic, const float* __restrict__ iv,
        int EU, int EI, float* __restrict__ out, int N_, int U_) {
    int group = blockIdx.x >> 2;
    int role  = blockIdx.x & 3;

    if (role == 3) {
        int ET = EU + EI;
        for (int e = group * TPB + threadIdx.x; e < ET; e += GROUPS * TPB) {
            int key, c; float v;
            if (e < EU) {
                key = N_ + __ldcs(ur + e);       c = __ldcs(uc + e);        v = __ldcs(uv + e);
            } else {
                int k = e - EU;
                key = N_ + U_ + __ldcs(ir + k);  c = U_ + __ldcs(ic + k);   v = __ldcs(iv + k);
            }
            scatter_edge(key, c, v);
        }
    } else {
        int tid    = (group * 3 + role) * TPB + threadIdx.x;
        int rr     = tid >> 4;
        int lane16 = tid & 15;
        if (rr >= N_) return;
        process_row(rr, lane16, threadIdx.x & 16, out);
    }
}

// ---------------- P3: user+item main ----------------------------------------
__global__ void __launch_bounds__(TPB) main_ui(float* __restrict__ out,
                                               int N_, int U_, int I_) {
    int tid    = blockIdx.x * TPB + threadIdx.x;
    int rr     = tid >> 4;
    int lane16 = tid & 15;
    if (rr >= U_ + I_) return;
    process_row(N_ + rr, lane16, threadIdx.x & 16, out);
}

// ---------------- overflow fixup (exactness; ~12K edges expected) -----------
__global__ void __launch_bounds__(TPB) fixup(float* __restrict__ out) {
    int n = min(d_ovf_count, OVF_CAP);
    long long total = (long long)n * 16;
    for (long long t = blockIdx.x * (long long)TPB + threadIdx.x; t < total;
         t += (long long)gridDim.x * TPB) {
        int idx  = (int)(t >> 4);
        int lane = (int)(t & 15);
        int4 e = d_ovf[idx];
        int key = e.x, c = e.y;
        float v = __int_as_float(e.z);
        uint2 g = d_emb16[(size_t)c * 16 + lane];
        float2 f0 = __half22float2(*reinterpret_cast<__half2*>(&g.x));
        float2 f1 = __half22float2(*reinterpret_cast<__half2*>(&g.y));
        float4 x = make_float4(v * f0.x, v * f0.y, v * f1.x, v * f1.y);
        float4* d = reinterpret_cast<float4*>(out + (long long)key * D64) + lane;
        asm volatile("red.global.add.v4.f32 [%0], {%1,%2,%3,%4};"
                     :: "l"(d), "f"(x.x), "f"(x.y), "f"(x.z), "f"(x.w)
                     : "memory");
    }
}

extern "C" void kernel_launch(void* const* d_in, const int* in_sizes, int n_in,
                              void* d_out, int out_size) {
    const float* user_emb = (const float*)d_in[0];
    const float* item_emb = (const float*)d_in[1];
    const int*   g_rows = (const int*)d_in[2];
    const int*   g_cols = (const int*)d_in[3];
    const float* g_vals = (const float*)d_in[4];
    const int*   u_rows = (const int*)d_in[5];
    const int*   u_cols = (const int*)d_in[6];
    const float* u_vals = (const float*)d_in[7];
    const int*   i_rows = (const int*)d_in[8];
    const int*   i_cols = (const int*)d_in[9];
    const float* i_vals = (const float*)d_in[10];

    float* out = (float*)d_out;

    const int U_ = in_sizes[0] / D64;   // 100000
    const int I_ = in_sizes[1] / D64;   // 50000
    const int N_ = U_ + I_;
    const int EG = in_sizes[2];
    const int EU = in_sizes[5];
    const int EI = in_sizes[8];
    const int ROWS = N_ + U_ + I_;

    // Zero cursors + overflow counter.
    void* curs_ptr = nullptr;
    cudaGetSymbolAddress(&curs_ptr, d_curs);
    cudaMemsetAsync(curs_ptr, 0, (size_t)ROWS * sizeof(int), 0);
    void* ovf_ptr = nullptr;
    cudaGetSymbolAddress(&ovf_ptr, d_ovf_count);
    cudaMemsetAsync(ovf_ptr, 0, sizeof(int), 0);

    // P1: fp16 table conversion (LTS-streaming) interleaved with graph
    // scatter (wavefront-bound).
    p1_convert_scatg<<<IBLOCKS, TPB>>>(user_emb, item_emb,
                                       g_rows, g_cols, g_vals, EG, U_);

    // P2: user/item scatter interleaved with graph main.
    p2_scatui_maing<<<IBLOCKS, TPB>>>(u_rows, u_cols, u_vals,
                                      i_rows, i_cols, i_vals,
                                      EU, EI, out, N_, U_);

    // P3: user+item main.
    {
        int n_rows = U_ + I_;
        int blocks = (n_rows * 16 + TPB - 1) / TPB;
        main_ui<<<blocks, TPB>>>(out, N_, U_, I_);
    }

    // Exact overflow fixup.
    fixup<<<1024, TPB>>>(out);
}